// round 3
// baseline (speedup 1.0000x reference)
#include <cuda_runtime.h>
#include <cuda_bf16.h>

#define N_SYSTEMS 16
#define D 64
#define NWARPS 8           // warps per block
#define NBLOCKS 888        // 148 SMs * 6 blocks (32.5 KB smem each)

// Global scratch. Zero-initialized at module load; finalize_kernel re-zeroes
// after each use, so the "zero at accumulate-entry" invariant holds across
// graph replays without a dedicated zeroing launch.
__device__ float g_sums[N_SYSTEMS * D];
__device__ float g_counts[N_SYSTEMS];

// Warp processes a QUAD of rows per iteration:
//   pair A: lanes 0-15 -> row 4t,   lanes 16-31 -> row 4t+1
//   pair B: lanes 0-15 -> row 4t+2, lanes 16-31 -> row 4t+3
// Two consecutive LDG.128 warp-instructions = 1024B, fully coalesced.
// Accumulation into per-warp private shared buffers (no atomics).
__global__ void __launch_bounds__(256) accumulate_kernel(
    const float* __restrict__ out, const int* __restrict__ system, int n_rows)
{
    __shared__ float4 ssum4[NWARPS][N_SYSTEMS][16];  // 32 KB
    __shared__ float  scount[NWARPS][N_SYSTEMS];     // 512 B

    const int tid  = threadIdx.x;
    const int lane = tid & 31;
    const int warp = tid >> 5;
    const int half = lane >> 4;      // which row of the pair
    const int q    = lane & 15;      // float4 index within row

    // Zero private accumulators.
    {
        float4* z = &ssum4[0][0][0];
        for (int i = tid; i < NWARPS * N_SYSTEMS * 16; i += 256)
            z[i] = make_float4(0.f, 0.f, 0.f, 0.f);
        if (tid < NWARPS * N_SYSTEMS) (&scount[0][0])[tid] = 0.0f;
    }
    __syncthreads();

    const float4* __restrict__ out4 = (const float4*)out;
    const long long nquads = ((long long)n_rows + 3) >> 2;
    const long long total_warps = (long long)gridDim.x * NWARPS;
    long long t = (long long)blockIdx.x * NWARPS + warp;

    // Processes one pair: s = normalized float4 chunk, code = sys or -1.
    auto accum_pair = [&](float4 v, int code) {
        // Sum of squares per row: width-16 butterfly (covers both rows).
        float ss = v.x * v.x + v.y * v.y + v.z * v.z + v.w * v.w;
        ss += __shfl_xor_sync(0xFFFFFFFFu, ss, 8);
        ss += __shfl_xor_sync(0xFFFFFFFFu, ss, 4);
        ss += __shfl_xor_sync(0xFFFFFFFFu, ss, 2);
        ss += __shfl_xor_sync(0xFFFFFFFFu, ss, 1);
        float inv = rsqrtf(fmaxf(ss, 1e-24f));   // == 1/max(||x||, 1e-12)

        float4 s;
        s.x = v.x * inv; s.y = v.y * inv; s.z = v.z * inv; s.w = v.w * inv;

        int other = __shfl_xor_sync(0xFFFFFFFFu, code, 16);
        if (!(code >= 0 && other == code)) {
            // Common path: halves hit distinct systems (or one invalid).
            if (code >= 0) {
                float4 a = ssum4[warp][code][q];
                a.x += s.x; a.y += s.y; a.z += s.z; a.w += s.w;
                ssum4[warp][code][q] = a;
                if (q == 0) scount[warp][code] += 1.0f;  // lanes 0 & 16 differ
            }
        } else {
            // Rare path (~1/16): both halves same system; combine to lower.
            s.x += __shfl_xor_sync(0xFFFFFFFFu, s.x, 16);
            s.y += __shfl_xor_sync(0xFFFFFFFFu, s.y, 16);
            s.z += __shfl_xor_sync(0xFFFFFFFFu, s.z, 16);
            s.w += __shfl_xor_sync(0xFFFFFFFFu, s.w, 16);
            if (half == 0) {
                float4 a = ssum4[warp][code][q];
                a.x += s.x; a.y += s.y; a.z += s.z; a.w += s.w;
                ssum4[warp][code][q] = a;
                if (q == 0) scount[warp][code] += 2.0f;
            }
        }
    };

    // Fetch quad t into (va, vb, ca, cb).
    auto fetch = [&](long long tt, float4& va, float4& vb, int& ca, int& cb) {
        va = make_float4(0.f, 0.f, 0.f, 0.f);
        vb = va; ca = -1; cb = -1;
        long long rowA = 4 * tt + half;
        long long rowB = rowA + 2;
        if (rowA < n_rows) {
            va = __ldcs(&out4[tt * 64 + lane]);
            ca = system[rowA];
        }
        if (rowB < n_rows) {
            vb = __ldcs(&out4[tt * 64 + 32 + lane]);
            cb = system[rowB];
        }
    };

    float4 va, vb; int ca, cb;
    if (t < nquads) fetch(t, va, vb, ca, cb);

    while (t < nquads) {
        long long tn = t + total_warps;
        float4 van, vbn; int can, cbn;
        if (tn < nquads) fetch(tn, van, vbn, can, cbn);

        accum_pair(va, ca);
        accum_pair(vb, cb);

        va = van; vb = vbn; ca = can; cb = cbn; t = tn;
    }

    __syncthreads();

    // Block flush: reduce the NWARPS private copies, one global atomic each.
    const float* sf = (const float*)&ssum4[0][0][0];   // [NWARPS][1024]
    for (int i = tid; i < N_SYSTEMS * D; i += 256) {
        float acc = 0.0f;
        #pragma unroll
        for (int w = 0; w < NWARPS; w++) acc += sf[w * (N_SYSTEMS * D) + i];
        if (acc != 0.0f) atomicAdd(&g_sums[i], acc);
    }
    if (tid < N_SYSTEMS) {
        float c = 0.0f;
        #pragma unroll
        for (int w = 0; w < NWARPS; w++) c += scount[w][tid];
        if (c != 0.0f) atomicAdd(&g_counts[tid], c);
    }
}

// Single-block epilogue: means -> Gram -> distance matrix, then re-zero
// the global scratch for the next call/replay.
__global__ void __launch_bounds__(256) finalize_kernel(float* __restrict__ dist)
{
    __shared__ float means[N_SYSTEMS * D];
    int t = threadIdx.x;

    for (int i = t; i < N_SYSTEMS * D; i += 256) {
        int s = i / D;
        means[i] = g_sums[i] / g_counts[s];
    }
    __syncthreads();

    // Re-zero scratch (all reads of g_* are done).
    for (int i = t; i < N_SYSTEMS * D; i += 256) g_sums[i] = 0.0f;
    if (t < N_SYSTEMS) g_counts[t] = 0.0f;

    int i = t >> 4;
    int j = t & 15;
    float dot = 0.0f;
    #pragma unroll
    for (int d = 0; d < D; d++)
        dot += means[i * D + d] * means[j * D + d];

    float v = 0.5f - 0.5f * dot;
    if (i == j) v = 0.0f;
    dist[i * N_SYSTEMS + j] = v;
}

extern "C" void kernel_launch(void* const* d_in, const int* in_sizes, int n_in,
                              void* d_out, int out_size) {
    const float* out_mat = (const float*)d_in[0];
    const int* system = (const int*)d_in[1];
    float* dist = (float*)d_out;
    int n_rows = in_sizes[1];  // system has one entry per row

    accumulate_kernel<<<NBLOCKS, 256>>>(out_mat, system, n_rows);
    finalize_kernel<<<1, 256>>>(dist);
}